// round 6
// baseline (speedup 1.0000x reference)
#include <cuda_runtime.h>

#define THREADS 128
#define BWARPS 4

typedef unsigned long long ull;

__constant__ float cW1[40];   // [4][10] feature-major
__constant__ float cb1[10];
__constant__ float cW2[190];  // [10][19]
__constant__ float cb2[19];

__device__ __forceinline__ ull pack2(float lo, float hi) {
    ull r; asm("mov.b64 %0, {%1, %2};" : "=l"(r) : "f"(lo), "f"(hi)); return r;
}
__device__ __forceinline__ void unpack2(ull v, float& lo, float& hi) {
    asm("mov.b64 {%0, %1}, %2;" : "=f"(lo), "=f"(hi) : "l"(v));
}
__device__ __forceinline__ ull ffma2(ull a, ull b, ull c) {
    ull d; asm("fma.rn.f32x2 %0, %1, %2, %3;" : "=l"(d) : "l"(a), "l"(b), "l"(c)); return d;
}

__global__ void __launch_bounds__(THREADS, 5) edge_mlp_kernel(
    const float* __restrict__ src, const float* __restrict__ dst,
    const float* __restrict__ eat, const float* __restrict__ u,
    const int*   __restrict__ batch,
    float* __restrict__ out, int E, int B)
{
    __shared__ __align__(16) float u_s[4096];
    __shared__ __align__(16) float stg[BWARPS][64 * 19];

    const int t = threadIdx.x;
    const int Bc = (B < 4096) ? B : 4096;

    for (int i = t; i < Bc; i += THREADS) u_s[i] = u[i];
    __syncthreads();

    const int warp = t >> 5, lane = t & 31;
    const int wg = blockIdx.x * BWARPS + warp;
    const int nw = gridDim.x * BWARPS;
    const int ntiles = (E + 127) >> 7;   // 128-edge tiles
    float* myst = stg[warp];

    for (int tile = wg; tile < ntiles; tile += nw) {
        const int base = tile << 7;
        if (base + 128 <= E) {
            // Front-batch ALL loads for 4 edges/thread
            float sv[4], dv[4], av[4], uv[4];
            int iv[4];
#pragma unroll
            for (int q = 0; q < 4; q++) {
                const int e = base + q * 32 + lane;
                sv[q] = src[e]; dv[q] = dst[e]; av[q] = eat[e]; iv[q] = batch[e];
            }
#pragma unroll
            for (int q = 0; q < 4; q++)
                uv[q] = ((unsigned)iv[q] < (unsigned)Bc) ? u_s[iv[q]] : __ldg(&u[iv[q]]);

#pragma unroll
            for (int p = 0; p < 2; p++) {
                const float f0[4] = {sv[2 * p], dv[2 * p], av[2 * p], uv[2 * p]};
                const float f1[4] = {sv[2 * p + 1], dv[2 * p + 1], av[2 * p + 1], uv[2 * p + 1]};

                // Layer 1: weights from constant port (LDCU, off the L1 crossbar)
                float x0[10], x1[10];
#pragma unroll
                for (int j = 0; j < 10; j++) { x0[j] = cb1[j]; x1[j] = cb1[j]; }
#pragma unroll
                for (int f = 0; f < 4; f++) {
                    const float v0 = f0[f], v1 = f1[f];
#pragma unroll
                    for (int j = 0; j < 10; j++) {
                        const float w = cW1[f * 10 + j];
                        x0[j] = fmaf(v0, w, x0[j]);
                        x1[j] = fmaf(v1, w, x1[j]);
                    }
                }

                // ReLU + broadcast-pack
                ull ph0[10], ph1[10];
#pragma unroll
                for (int j = 0; j < 10; j++) {
                    float h0 = fmaxf(x0[j], 0.f), h1 = fmaxf(x1[j], 0.f);
                    ph0[j] = pack2(h0, h0);
                    ph1[j] = pack2(h1, h1);
                }

                // Layer 2: 5 groups of 4 columns via fma.rn.f32x2; weights via LDCU + pack
#pragma unroll
                for (int kg = 0; kg < 5; kg++) {
                    const int k0 = kg * 4;
                    const ull bx = pack2(cb2[k0], cb2[k0 + 1]);
                    const ull by = (kg < 4) ? pack2(cb2[k0 + 2], cb2[k0 + 3])
                                            : pack2(cb2[18], 0.f);
                    ull a00 = bx, a01 = by;
                    ull a10 = bx, a11 = by;
#pragma unroll
                    for (int j = 0; j < 10; j++) {
                        const float w0 = cW2[j * 19 + k0];
                        const float w1 = cW2[j * 19 + k0 + 1];
                        const float w2 = (kg < 4) ? cW2[j * 19 + k0 + 2] : cW2[j * 19 + 18];
                        const float w3 = (kg < 4) ? cW2[j * 19 + k0 + 3] : 0.f;
                        const ull wx = pack2(w0, w1);
                        const ull wy = pack2(w2, w3);
                        a00 = ffma2(ph0[j], wx, a00);
                        a01 = ffma2(ph0[j], wy, a01);
                        a10 = ffma2(ph1[j], wx, a10);
                        a11 = ffma2(ph1[j], wy, a11);
                    }
                    float pp, qq;
                    if (kg < 4) {
                        unpack2(a00, pp, qq);
                        myst[lane * 19 + k0] = pp; myst[lane * 19 + k0 + 1] = qq;
                        unpack2(a01, pp, qq);
                        myst[lane * 19 + k0 + 2] = pp; myst[lane * 19 + k0 + 3] = qq;
                        unpack2(a10, pp, qq);
                        myst[(lane + 32) * 19 + k0] = pp; myst[(lane + 32) * 19 + k0 + 1] = qq;
                        unpack2(a11, pp, qq);
                        myst[(lane + 32) * 19 + k0 + 2] = pp; myst[(lane + 32) * 19 + k0 + 3] = qq;
                    } else {
                        // k16,k17 from first pair; k18 = lo of second pair
                        unpack2(a00, pp, qq);
                        myst[lane * 19 + 16] = pp; myst[lane * 19 + 17] = qq;
                        unpack2(a01, pp, qq);
                        myst[lane * 19 + 18] = pp;
                        unpack2(a10, pp, qq);
                        myst[(lane + 32) * 19 + 16] = pp; myst[(lane + 32) * 19 + 17] = qq;
                        unpack2(a11, pp, qq);
                        myst[(lane + 32) * 19 + 18] = pp;
                    }
                }

                __syncwarp();
                // Copy out this 64-edge half: 64*19 = 1216 floats = 304 float4
                const float4* s4 = (const float4*)myst;
                float4* o4 = (float4*)(out + (size_t)(base + p * 64) * 19);
#pragma unroll 1
                for (int i = lane; i < 304; i += 32) o4[i] = s4[i];
                __syncwarp();
            }
        } else {
            // Tail tile
            for (int e = base + lane; e < E; e += 32) {
                float s = src[e], d = dst[e], a = eat[e];
                int bi = batch[e];
                float uu = ((unsigned)bi < (unsigned)Bc) ? u_s[bi] : __ldg(&u[bi]);
                float feat[4] = {s, d, a, uu};
                float h[10];
#pragma unroll
                for (int j = 0; j < 10; j++) {
                    float x = cb1[j];
#pragma unroll
                    for (int f = 0; f < 4; f++) x = fmaf(feat[f], cW1[f * 10 + j], x);
                    h[j] = fmaxf(x, 0.f);
                }
#pragma unroll
                for (int k = 0; k < 19; k++) {
                    float acc = cb2[k];
#pragma unroll
                    for (int j = 0; j < 10; j++) acc = fmaf(h[j], cW2[j * 19 + k], acc);
                    out[(size_t)e * 19 + k] = acc;
                }
            }
        }
    }
}

extern "C" void kernel_launch(void* const* d_in, const int* in_sizes, int n_in,
                              void* d_out, int out_size) {
    const float* src   = (const float*)d_in[0];
    const float* dst   = (const float*)d_in[1];
    const float* eat   = (const float*)d_in[2];
    const float* u     = (const float*)d_in[3];
    const int*   batch = (const int*)d_in[4];
    const int E = in_sizes[0];
    const int B = in_sizes[3];

    // Stage weights into constant memory (D2D async copies: graph-capturable)
    cudaMemcpyToSymbolAsync(cW1, d_in[5], 40 * sizeof(float), 0, cudaMemcpyDeviceToDevice, 0);
    cudaMemcpyToSymbolAsync(cb1, d_in[6], 10 * sizeof(float), 0, cudaMemcpyDeviceToDevice, 0);
    cudaMemcpyToSymbolAsync(cW2, d_in[7], 190 * sizeof(float), 0, cudaMemcpyDeviceToDevice, 0);
    cudaMemcpyToSymbolAsync(cb2, d_in[8], 19 * sizeof(float), 0, cudaMemcpyDeviceToDevice, 0);

    edge_mlp_kernel<<<740, THREADS>>>(src, dst, eat, u, batch, (float*)d_out, E, B);
}

// round 7
// speedup vs baseline: 5.0405x; 5.0405x over previous
#include <cuda_runtime.h>

#define THREADS 128
#define BWARPS 4

typedef unsigned long long ull;

// float offsets into dynamic smem
#define OFF_U    0                     // 4096 floats
#define OFF_W1   4096                  // 48 (4 rows x 12)
#define OFF_B1D  4144                  // 24 (10 dup pairs + pad)
#define OFF_B2D  4168                  // 40 (19 dup pairs + pad)
#define OFF_W2   4208                  // 200 (10 x 20, col 19 = 0)
#define OFF_STG  4408                  // BWARPS x 2432
#define SMEM_FLOATS (OFF_STG + BWARPS * 2432)
#define SMEM_BYTES (SMEM_FLOATS * 4)

__device__ __forceinline__ ull pack2(float lo, float hi) {
    ull r; asm("mov.b64 %0, {%1, %2};" : "=l"(r) : "f"(lo), "f"(hi)); return r;
}
__device__ __forceinline__ void unpack2(ull v, float& lo, float& hi) {
    asm("mov.b64 {%0, %1}, %2;" : "=f"(lo), "=f"(hi) : "l"(v));
}
__device__ __forceinline__ ull ffma2(ull a, ull b, ull c) {
    ull d; asm("fma.rn.f32x2 %0, %1, %2, %3;" : "=l"(d) : "l"(a), "l"(b), "l"(c)); return d;
}

__global__ void __launch_bounds__(THREADS, 4) edge_mlp_kernel(
    const float* __restrict__ src, const float* __restrict__ dst,
    const float* __restrict__ eat, const float* __restrict__ u,
    const int*   __restrict__ batch,
    const float* __restrict__ W1, const float* __restrict__ b1,
    const float* __restrict__ W2, const float* __restrict__ b2,
    float* __restrict__ out, int E, int B)
{
    extern __shared__ __align__(16) float sm[];
    float* u_s = sm + OFF_U;
    const float* W1s = sm + OFF_W1;
    const float* b1d = sm + OFF_B1D;
    const float* b2d = sm + OFF_B2D;
    const float* W2p = sm + OFF_W2;

    const int t = threadIdx.x;
    const int Bc = (B < 4096) ? B : 4096;

    for (int i = t; i < Bc; i += THREADS) u_s[i] = u[i];
    if (t < 48) { int f = t / 12, j = t % 12; sm[OFF_W1 + t] = (j < 10) ? W1[f * 10 + j] : 0.f; }
    if (t < 24) sm[OFF_B1D + t] = (t < 20) ? b1[t >> 1] : 0.f;
    if (t < 40) sm[OFF_B2D + t] = (t < 38) ? b2[t >> 1] : 0.f;
    for (int i = t; i < 200; i += THREADS) {
        int j = i / 20, k = i % 20;
        sm[OFF_W2 + i] = (k < 19) ? W2[j * 19 + k] : 0.f;
    }
    __syncthreads();

    const int warp = t >> 5, lane = t & 31;
    const int wg = blockIdx.x * BWARPS + warp;
    const int nw = gridDim.x * BWARPS;
    const int ntiles = (E + 127) >> 7;
    float* myst = sm + OFF_STG + warp * 2432;

    for (int tile = wg; tile < ntiles; tile += nw) {
        const int base = tile << 7;
        if (base + 128 <= E) {
            // Front-batch all loads: 4 edges/thread (rows lane, lane+32, lane+64, lane+96)
            float sv[4], dv[4], av[4], uv[4];
            int iv[4];
#pragma unroll
            for (int q = 0; q < 4; q++) {
                const int e = base + q * 32 + lane;
                sv[q] = src[e]; dv[q] = dst[e]; av[q] = eat[e]; iv[q] = batch[e];
            }
#pragma unroll
            for (int q = 0; q < 4; q++)
                uv[q] = ((unsigned)iv[q] < (unsigned)Bc) ? u_s[iv[q]] : __ldg(&u[iv[q]]);

            // Edge-pair packed inputs: pair0=(q0,q1), pair1=(q2,q3)
            ull pv[2][4];
#pragma unroll
            for (int pr = 0; pr < 2; pr++) {
                pv[pr][0] = pack2(sv[2 * pr], sv[2 * pr + 1]);
                pv[pr][1] = pack2(dv[2 * pr], dv[2 * pr + 1]);
                pv[pr][2] = pack2(av[2 * pr], av[2 * pr + 1]);
                pv[pr][3] = pack2(uv[2 * pr], uv[2 * pr + 1]);
            }

            // Layer 1: px[pr][j] = (x_e0[j], x_e1[j]), one weight pass for all 4 edges
            ull px[2][10];
#pragma unroll
            for (int jg = 0; jg < 5; jg++) {
                const ulonglong2 bb = *(const ulonglong2*)&b1d[jg * 4];
                px[0][2 * jg] = bb.x; px[0][2 * jg + 1] = bb.y;
                px[1][2 * jg] = bb.x; px[1][2 * jg + 1] = bb.y;
            }
#pragma unroll
            for (int f = 0; f < 4; f++) {
                const float4 wA = *(const float4*)&W1s[f * 12 + 0];
                const float4 wB = *(const float4*)&W1s[f * 12 + 4];
                const float4 wC = *(const float4*)&W1s[f * 12 + 8];
                const float wj[10] = {wA.x, wA.y, wA.z, wA.w, wB.x, wB.y, wB.z, wB.w, wC.x, wC.y};
#pragma unroll
                for (int j = 0; j < 10; j++) {
                    const ull w = pack2(wj[j], wj[j]);
                    px[0][j] = ffma2(pv[0][f], w, px[0][j]);
                    px[1][j] = ffma2(pv[1][f], w, px[1][j]);
                }
            }

            // ReLU in place
#pragma unroll
            for (int pr = 0; pr < 2; pr++)
#pragma unroll
                for (int j = 0; j < 10; j++) {
                    float a, b;
                    unpack2(px[pr][j], a, b);
                    px[pr][j] = pack2(fmaxf(a, 0.f), fmaxf(b, 0.f));
                }

            // Layer 2: one weight pass, 4 k's per group, both edge pairs
#pragma unroll
            for (int kg = 0; kg < 5; kg++) {
                const int k0 = kg * 4;
                const ulonglong2 b01 = *(const ulonglong2*)&b2d[2 * k0];
                const ulonglong2 b23 = *(const ulonglong2*)&b2d[2 * k0 + 4];
                ull acc[2][4];
                acc[0][0] = b01.x; acc[0][1] = b01.y; acc[0][2] = b23.x; acc[0][3] = b23.y;
                acc[1][0] = b01.x; acc[1][1] = b01.y; acc[1][2] = b23.x; acc[1][3] = b23.y;
#pragma unroll
                for (int j = 0; j < 10; j++) {
                    const float4 w4 = *(const float4*)&W2p[j * 20 + k0];
                    const ull w0 = pack2(w4.x, w4.x), w1 = pack2(w4.y, w4.y);
                    const ull w2 = pack2(w4.z, w4.z), w3 = pack2(w4.w, w4.w);
                    acc[0][0] = ffma2(px[0][j], w0, acc[0][0]);
                    acc[0][1] = ffma2(px[0][j], w1, acc[0][1]);
                    acc[0][2] = ffma2(px[0][j], w2, acc[0][2]);
                    acc[0][3] = ffma2(px[0][j], w3, acc[0][3]);
                    acc[1][0] = ffma2(px[1][j], w0, acc[1][0]);
                    acc[1][1] = ffma2(px[1][j], w1, acc[1][1]);
                    acc[1][2] = ffma2(px[1][j], w2, acc[1][2]);
                    acc[1][3] = ffma2(px[1][j], w3, acc[1][3]);
                }
                const int kn = (kg < 4) ? 4 : 3;
#pragma unroll
                for (int pr = 0; pr < 2; pr++) {
                    const int r0 = lane + pr * 64, r1 = r0 + 32;
#pragma unroll
                    for (int m = 0; m < 4; m++) {
                        if (m < kn) {
                            float lo, hi;
                            unpack2(acc[pr][m], lo, hi);
                            myst[r0 * 19 + k0 + m] = lo;   // edge 2pr
                            myst[r1 * 19 + k0 + m] = hi;   // edge 2pr+1
                        }
                    }
                }
            }

            __syncwarp();
            // Copy out 128*19 = 2432 floats = 608 float4 (16B-aligned both sides)
            const float4* s4 = (const float4*)myst;
            float4* o4 = (float4*)(out + (size_t)base * 19);
#pragma unroll 1
            for (int i = lane; i < 608; i += 32) o4[i] = s4[i];
            __syncwarp();
        } else {
            // Tail tile: scalar fallback
            for (int e = base + lane; e < E; e += 32) {
                float s = src[e], d = dst[e], a = eat[e];
                int bi = batch[e];
                float uu = ((unsigned)bi < (unsigned)Bc) ? u_s[bi] : __ldg(&u[bi]);
                float feat[4] = {s, d, a, uu};
                float h[10];
#pragma unroll
                for (int j = 0; j < 10; j++) {
                    float x = b1d[2 * j];
#pragma unroll
                    for (int f = 0; f < 4; f++) x = fmaf(feat[f], W1s[f * 12 + j], x);
                    h[j] = fmaxf(x, 0.f);
                }
#pragma unroll
                for (int k = 0; k < 19; k++) {
                    float acc = b2d[2 * k];
#pragma unroll
                    for (int j = 0; j < 10; j++) acc = fmaf(h[j], W2p[j * 20 + k], acc);
                    out[(size_t)e * 19 + k] = acc;
                }
            }
        }
    }
}

extern "C" void kernel_launch(void* const* d_in, const int* in_sizes, int n_in,
                              void* d_out, int out_size) {
    const float* src   = (const float*)d_in[0];
    const float* dst   = (const float*)d_in[1];
    const float* eat   = (const float*)d_in[2];
    const float* u     = (const float*)d_in[3];
    const int*   batch = (const int*)d_in[4];
    const float* W1    = (const float*)d_in[5];
    const float* b1    = (const float*)d_in[6];
    const float* W2    = (const float*)d_in[7];
    const float* b2    = (const float*)d_in[8];
    const int E = in_sizes[0];
    const int B = in_sizes[3];

    cudaFuncSetAttribute(edge_mlp_kernel,
                         cudaFuncAttributeMaxDynamicSharedMemorySize, SMEM_BYTES);

    edge_mlp_kernel<<<592, THREADS, SMEM_BYTES>>>(src, dst, eat, u, batch,
                                                  W1, b1, W2, b2, (float*)d_out, E, B);
}